// round 1
// baseline (speedup 1.0000x reference)
#include <cuda_runtime.h>
#include <cstddef>

#define NL 6
#define NH 16
#define CD 1024
#define HSD 64
#define FFD 4096
#define NV 67
#define NB 8
#define NT 1024
#define NM (NB*NT)   // 8192 rows

typedef unsigned long long u64;

// ------------------------- scratch (device globals, no allocation) ---------
__device__ float g_x [(size_t)NM*CD];
__device__ float g_h [(size_t)NM*CD];
__device__ float g_q [(size_t)NM*CD];
__device__ float g_k [(size_t)NM*CD];
__device__ float g_v [(size_t)NM*CD];
__device__ float g_o [(size_t)NM*CD];
__device__ float g_ff[(size_t)NM*FFD];

__device__ __forceinline__ float* buf(int which) {
    switch (which) {
        case 0: return g_x;
        case 1: return g_h;
        case 2: return g_q;
        case 3: return g_k;
        case 4: return g_v;
        case 5: return g_o;
        default: return g_ff;
    }
}

// ------------------------- embedding ---------------------------------------
__global__ void __launch_bounds__(256) embed_kernel(
        const int* __restrict__ idx, const float* __restrict__ tok,
        const float* __restrict__ pos) {
    int row = blockIdx.x;
    int t = row & (NT - 1);
    int token = idx[row];
    const float4* t4 = (const float4*)(tok + (size_t)token * CD);
    const float4* p4 = (const float4*)(pos + (size_t)t * CD);
    float4 a = t4[threadIdx.x];
    float4 b = p4[threadIdx.x];
    a.x += b.x; a.y += b.y; a.z += b.z; a.w += b.w;
    ((float4*)(g_x + (size_t)row * CD))[threadIdx.x] = a;
}

// ------------------------- layernorm ---------------------------------------
__global__ void __launch_bounds__(256) ln_kernel(
        int src, const float* __restrict__ g, const float* __restrict__ b, int dst) {
    __shared__ float rs[8], rss[8];
    __shared__ float mean_s, rstd_s;
    const float* x = buf(src);
    float* out = buf(dst);
    int row = blockIdx.x, tid = threadIdx.x;
    float4 v = ((const float4*)(x + (size_t)row * CD))[tid];
    float s  = v.x + v.y + v.z + v.w;
    float ss = v.x*v.x + v.y*v.y + v.z*v.z + v.w*v.w;
    #pragma unroll
    for (int o = 16; o; o >>= 1) {
        s  += __shfl_xor_sync(0xffffffffu, s,  o);
        ss += __shfl_xor_sync(0xffffffffu, ss, o);
    }
    if ((tid & 31) == 0) { rs[tid >> 5] = s; rss[tid >> 5] = ss; }
    __syncthreads();
    if (tid == 0) {
        float S = 0.f, SS = 0.f;
        #pragma unroll
        for (int i = 0; i < 8; i++) { S += rs[i]; SS += rss[i]; }
        float mean = S * (1.f / CD);
        float var  = SS * (1.f / CD) - mean * mean;
        mean_s = mean;
        rstd_s = rsqrtf(var + 1e-5f);
    }
    __syncthreads();
    float mean = mean_s, rstd = rstd_s;
    float4 gg = ((const float4*)g)[tid];
    float4 bb = ((const float4*)b)[tid];
    float4 o4;
    o4.x = (v.x - mean) * rstd * gg.x + bb.x;
    o4.y = (v.y - mean) * rstd * gg.y + bb.y;
    o4.z = (v.z - mean) * rstd * gg.z + bb.z;
    o4.w = (v.w - mean) * rstd * gg.w + bb.w;
    ((float4*)(out + (size_t)row * CD))[tid] = o4;
}

// ------------------------- SGEMM (f32x2 packed FMA) ------------------------
// out[M,N] = act(A[M,K] @ W[K,N] + bias) (+res). Tiles: 128x128x8, 256 thr,
// 8x8 per thread, accumulators packed into fma.rn.f32x2 pairs along N.
template<bool RELU, bool RES>
__global__ void __launch_bounds__(256) sgemm_kernel(
        int asel, const float* __restrict__ W,
        const float* __restrict__ bias, int rsel, int osel, int N, int K) {
    __shared__ float As[8][128];
    __shared__ float Bs[8][128];
    const float* A   = buf(asel);
    const float* res = buf(rsel);
    float* out       = buf(osel);

    int tid = threadIdx.x;
    int tx = tid & 15, ty = tid >> 4;
    const float* Ab = A + (size_t)blockIdx.y * 128 * K;
    const float* Wb = W + (size_t)blockIdx.x * 128;
    int arow = tid >> 1, acol = (tid & 1) << 2;
    int brow = tid >> 5, bcol = (tid & 31) << 2;

    float4 areg = *(const float4*)&Ab[(size_t)arow * K + acol];
    float4 breg = *(const float4*)&Wb[(size_t)brow * N + bcol];

    u64 acc[8][4];
    #pragma unroll
    for (int i = 0; i < 8; i++)
        #pragma unroll
        for (int j = 0; j < 4; j++) acc[i][j] = 0ull;

    for (int kt = 0; ; kt += 8) {
        As[acol + 0][arow] = areg.x;
        As[acol + 1][arow] = areg.y;
        As[acol + 2][arow] = areg.z;
        As[acol + 3][arow] = areg.w;
        *(float4*)&Bs[brow][bcol] = breg;
        __syncthreads();
        if (kt + 8 < K) {
            areg = *(const float4*)&Ab[(size_t)arow * K + (kt + 8) + acol];
            breg = *(const float4*)&Wb[(size_t)(kt + 8 + brow) * N + bcol];
        }
        #pragma unroll
        for (int k = 0; k < 8; k++) {
            float4 a0 = *(const float4*)&As[k][ty * 4];
            float4 a1 = *(const float4*)&As[k][64 + ty * 4];
            u64 b2[4];
            b2[0] = *(const u64*)&Bs[k][tx * 4];
            b2[1] = *(const u64*)&Bs[k][tx * 4 + 2];
            b2[2] = *(const u64*)&Bs[k][64 + tx * 4];
            b2[3] = *(const u64*)&Bs[k][64 + tx * 4 + 2];
            float af[8] = {a0.x, a0.y, a0.z, a0.w, a1.x, a1.y, a1.z, a1.w};
            u64 aa[8];
            #pragma unroll
            for (int i = 0; i < 8; i++) {
                unsigned ui = __float_as_uint(af[i]);
                asm("mov.b64 %0, {%1, %2};" : "=l"(aa[i]) : "r"(ui), "r"(ui));
            }
            #pragma unroll
            for (int i = 0; i < 8; i++)
                #pragma unroll
                for (int j = 0; j < 4; j++)
                    asm("fma.rn.f32x2 %0, %1, %2, %0;"
                        : "+l"(acc[i][j]) : "l"(aa[i]), "l"(b2[j]));
        }
        __syncthreads();
        if (kt + 8 >= K) break;
    }

    #pragma unroll
    for (int ih = 0; ih < 2; ih++)
    #pragma unroll
    for (int i = 0; i < 4; i++) {
        int m = blockIdx.y * 128 + ih * 64 + ty * 4 + i;
        #pragma unroll
        for (int jh = 0; jh < 2; jh++) {
            int n0 = blockIdx.x * 128 + jh * 64 + tx * 4;
            unsigned lo0, hi0, lo1, hi1;
            asm("mov.b64 {%0,%1}, %2;" : "=r"(lo0), "=r"(hi0) : "l"(acc[ih*4+i][jh*2+0]));
            asm("mov.b64 {%0,%1}, %2;" : "=r"(lo1), "=r"(hi1) : "l"(acc[ih*4+i][jh*2+1]));
            float c0 = __uint_as_float(lo0), c1 = __uint_as_float(hi0);
            float c2 = __uint_as_float(lo1), c3 = __uint_as_float(hi1);
            if (bias) {
                float4 bv = *(const float4*)&bias[n0];
                c0 += bv.x; c1 += bv.y; c2 += bv.z; c3 += bv.w;
            }
            if (RELU) {
                c0 = fmaxf(c0, 0.f); c1 = fmaxf(c1, 0.f);
                c2 = fmaxf(c2, 0.f); c3 = fmaxf(c3, 0.f);
            }
            if (RES) {
                float4 rv = *(const float4*)&res[(size_t)m * N + n0];
                c0 += rv.x; c1 += rv.y; c2 += rv.z; c3 += rv.w;
            }
            *(float4*)&out[(size_t)m * N + n0] = make_float4(c0, c1, c2, c3);
        }
    }
}

// ------------------------- flash attention (fp32) --------------------------
// grid: (B*H, T/64). Each block: 64 query rows, HS=64, iterates causal K tiles.
__global__ void __launch_bounds__(256) attn_kernel() {
    __shared__ float Qt[64][64];   // Q transposed [d][row]
    __shared__ float KP[64][64];   // K transposed [d][col], reused as P [row][col]
    __shared__ float Vs[64][64];   // V natural    [key][d]
    const float* q = g_q;
    const float* k = g_k;
    const float* v = g_v;
    float* o = g_o;

    int bh = blockIdx.x;
    int b = bh >> 4, h = bh & 15;
    int qb = blockIdx.y;
    int tid = threadIdx.x;
    int tx = tid & 15, ty = tid >> 4;
    const size_t base = (size_t)b * NT * CD + h * HSD;

    {   // load Q tile transposed
        int r0 = tid >> 4;
        int d0 = (tid & 15) * 4;
        #pragma unroll
        for (int rr = 0; rr < 64; rr += 16) {
            int r = r0 + rr;
            float4 t = *(const float4*)&q[base + (size_t)(qb * 64 + r) * CD + d0];
            Qt[d0 + 0][r] = t.x; Qt[d0 + 1][r] = t.y;
            Qt[d0 + 2][r] = t.z; Qt[d0 + 3][r] = t.w;
        }
    }

    float m_i[4], l_i[4], acc[4][4];
    #pragma unroll
    for (int i = 0; i < 4; i++) {
        m_i[i] = -1e30f; l_i[i] = 0.f;
        #pragma unroll
        for (int j = 0; j < 4; j++) acc[i][j] = 0.f;
    }
    const float scale = 0.125f;   // 1/sqrt(64)

    for (int kb = 0; kb <= qb; kb++) {
        __syncthreads();   // protect KP/Vs from previous iteration's readers
        {   // load K transposed + V natural
            int r0 = tid >> 4;
            int d0 = (tid & 15) * 4;
            #pragma unroll
            for (int rr = 0; rr < 64; rr += 16) {
                int r = r0 + rr;
                float4 t = *(const float4*)&k[base + (size_t)(kb * 64 + r) * CD + d0];
                KP[d0 + 0][r] = t.x; KP[d0 + 1][r] = t.y;
                KP[d0 + 2][r] = t.z; KP[d0 + 3][r] = t.w;
                float4 u = *(const float4*)&v[base + (size_t)(kb * 64 + r) * CD + d0];
                *(float4*)&Vs[r][d0] = u;
            }
        }
        __syncthreads();

        float s[4][4];
        #pragma unroll
        for (int i = 0; i < 4; i++)
            #pragma unroll
            for (int j = 0; j < 4; j++) s[i][j] = 0.f;
        for (int d = 0; d < 64; d++) {
            float4 a = *(const float4*)&Qt[d][ty * 4];
            float4 bb = *(const float4*)&KP[d][tx * 4];
            float av[4] = {a.x, a.y, a.z, a.w};
            float bv[4] = {bb.x, bb.y, bb.z, bb.w};
            #pragma unroll
            for (int i = 0; i < 4; i++)
                #pragma unroll
                for (int j = 0; j < 4; j++) s[i][j] += av[i] * bv[j];
        }
        if (kb == qb) {
            #pragma unroll
            for (int i = 0; i < 4; i++)
                #pragma unroll
                for (int j = 0; j < 4; j++)
                    s[i][j] = (tx * 4 + j > ty * 4 + i) ? -1e30f : s[i][j] * scale;
        } else {
            #pragma unroll
            for (int i = 0; i < 4; i++)
                #pragma unroll
                for (int j = 0; j < 4; j++) s[i][j] *= scale;
        }

        float p[4][4];
        #pragma unroll
        for (int i = 0; i < 4; i++) {
            float tm = fmaxf(fmaxf(s[i][0], s[i][1]), fmaxf(s[i][2], s[i][3]));
            #pragma unroll
            for (int off = 8; off; off >>= 1)
                tm = fmaxf(tm, __shfl_xor_sync(0xffffffffu, tm, off));
            float nm = fmaxf(m_i[i], tm);
            float corr = __expf(m_i[i] - nm);
            float rs = 0.f;
            #pragma unroll
            for (int j = 0; j < 4; j++) {
                p[i][j] = __expf(s[i][j] - nm);
                rs += p[i][j];
            }
            #pragma unroll
            for (int off = 8; off; off >>= 1)
                rs += __shfl_xor_sync(0xffffffffu, rs, off);
            l_i[i] = l_i[i] * corr + rs;
            m_i[i] = nm;
            #pragma unroll
            for (int j = 0; j < 4; j++) acc[i][j] *= corr;
        }

        __syncthreads();   // done reading KP as K-tile
        #pragma unroll
        for (int i = 0; i < 4; i++)
            *(float4*)&KP[ty * 4 + i][tx * 4] =
                make_float4(p[i][0], p[i][1], p[i][2], p[i][3]);
        __syncthreads();   // P visible

        for (int kk = 0; kk < 64; kk += 4) {
            float pr[4][4];
            #pragma unroll
            for (int i = 0; i < 4; i++) {
                float4 t = *(const float4*)&KP[ty * 4 + i][kk];
                pr[i][0] = t.x; pr[i][1] = t.y; pr[i][2] = t.z; pr[i][3] = t.w;
            }
            #pragma unroll
            for (int kq = 0; kq < 4; kq++) {
                float4 vv = *(const float4*)&Vs[kk + kq][tx * 4];
                #pragma unroll
                for (int i = 0; i < 4; i++) {
                    acc[i][0] += pr[i][kq] * vv.x;
                    acc[i][1] += pr[i][kq] * vv.y;
                    acc[i][2] += pr[i][kq] * vv.z;
                    acc[i][3] += pr[i][kq] * vv.w;
                }
            }
        }
    }

    #pragma unroll
    for (int i = 0; i < 4; i++) {
        float inv = 1.f / l_i[i];
        float4 r = make_float4(acc[i][0] * inv, acc[i][1] * inv,
                               acc[i][2] * inv, acc[i][3] * inv);
        *(float4*)&o[base + (size_t)(qb * 64 + ty * 4 + i) * CD + tx * 4] = r;
    }
}

// ------------------------- LM head (N=67) ----------------------------------
__global__ void __launch_bounds__(128) lm_kernel(
        const float* __restrict__ W, const float* __restrict__ bias,
        float* __restrict__ out) {
    __shared__ float hs[CD];
    const float* h = g_h;
    int row = blockIdx.x;
    int tid = threadIdx.x;
    ((float4*)hs)[tid]       = ((const float4*)(h + (size_t)row * CD))[tid];
    ((float4*)hs)[tid + 128] = ((const float4*)(h + (size_t)row * CD))[tid + 128];
    __syncthreads();
    if (tid < NV) {
        float a0 = 0.f, a1 = 0.f, a2 = 0.f, a3 = 0.f;
        #pragma unroll 4
        for (int kk = 0; kk < CD; kk += 4) {
            a0 += hs[kk + 0] * W[(kk + 0) * NV + tid];
            a1 += hs[kk + 1] * W[(kk + 1) * NV + tid];
            a2 += hs[kk + 2] * W[(kk + 2) * NV + tid];
            a3 += hs[kk + 3] * W[(kk + 3) * NV + tid];
        }
        out[(size_t)row * NV + tid] = bias[tid] + ((a0 + a1) + (a2 + a3));
    }
}

// ------------------------- launch ------------------------------------------
extern "C" void kernel_launch(void* const* d_in, const int* in_sizes, int n_in,
                              void* d_out, int out_size) {
    const int*   idx  = (const int*)  d_in[0];
    const float* tok  = (const float*)d_in[1];
    const float* pos  = (const float*)d_in[2];
    const float* Wq   = (const float*)d_in[3];
    const float* Wk   = (const float*)d_in[4];
    const float* Wv   = (const float*)d_in[5];
    const float* Wo   = (const float*)d_in[6];
    const float* bo   = (const float*)d_in[7];
    const float* ln1g = (const float*)d_in[8];
    const float* ln1b = (const float*)d_in[9];
    const float* ln2g = (const float*)d_in[10];
    const float* ln2b = (const float*)d_in[11];
    const float* W1   = (const float*)d_in[12];
    const float* b1   = (const float*)d_in[13];
    const float* W2   = (const float*)d_in[14];
    const float* b2   = (const float*)d_in[15];
    const float* lnfg = (const float*)d_in[16];
    const float* lnfb = (const float*)d_in[17];
    const float* Wlm  = (const float*)d_in[18];
    const float* blm  = (const float*)d_in[19];
    float* out = (float*)d_out;

    // buffer ids: 0=x 1=h 2=q 3=k 4=v 5=o 6=ff
    dim3 g1(CD / 128, NM / 128);    // (8, 64)
    dim3 g2(FFD / 128, NM / 128);   // (32, 64)

    embed_kernel<<<NM, 256>>>(idx, tok, pos);
    for (int l = 0; l < NL; l++) {
        ln_kernel<<<NM, 256>>>(0, ln1g + (size_t)l * CD, ln1b + (size_t)l * CD, 1);
        sgemm_kernel<false, false><<<g1, 256>>>(1, Wq + (size_t)l * CD * CD, nullptr, 0, 2, CD, CD);
        sgemm_kernel<false, false><<<g1, 256>>>(1, Wk + (size_t)l * CD * CD, nullptr, 0, 3, CD, CD);
        sgemm_kernel<false, false><<<g1, 256>>>(1, Wv + (size_t)l * CD * CD, nullptr, 0, 4, CD, CD);
        attn_kernel<<<dim3(NB * NH, NT / 64), 256>>>();
        sgemm_kernel<false, true ><<<g1, 256>>>(5, Wo + (size_t)l * CD * CD, bo + (size_t)l * CD, 0, 0, CD, CD);
        ln_kernel<<<NM, 256>>>(0, ln2g + (size_t)l * CD, ln2b + (size_t)l * CD, 1);
        sgemm_kernel<true,  false><<<g2, 256>>>(1, W1 + (size_t)l * CD * FFD, b1 + (size_t)l * FFD, 0, 6, FFD, CD);
        sgemm_kernel<false, true ><<<g1, 256>>>(6, W2 + (size_t)l * FFD * CD, b2 + (size_t)l * CD, 0, 0, CD, FFD);
    }
    ln_kernel<<<NM, 256>>>(0, lnfg, lnfb, 1);
    lm_kernel<<<NM, 128>>>(Wlm, blm, out);
}

// round 3
// speedup vs baseline: 2.3786x; 2.3786x over previous
#include <cuda_runtime.h>
#include <cuda_bf16.h>
#include <cstdint>
#include <cstddef>

#define NL 6
#define NH 16
#define CD 1024
#define HSD 64
#define FFD 4096
#define NV 67
#define NB 8
#define NT 1024
#define NM (NB*NT)   // 8192 rows

typedef unsigned long long u64;
typedef unsigned int u32;

// Arch-specific feature gate: tcgen05 only exists in the sm_103a cubin pass.
#if defined(__CUDA_ARCH__) && (defined(__CUDA_ARCH_FEAT_SM103_ALL) || defined(__CUDA_ARCH_SPECIFIC__))
#define HAS_TCGEN05 1
#else
#define HAS_TCGEN05 0
#endif

// ------------------------- scratch (device globals, no allocation) ---------
__device__ float g_x [(size_t)NM*CD];
__device__ float g_h [(size_t)NM*CD];
__device__ float g_q [(size_t)NM*CD];
__device__ float g_k [(size_t)NM*CD];
__device__ float g_v [(size_t)NM*CD];
__device__ float g_o [(size_t)NM*CD];
__device__ float g_ff[(size_t)NM*FFD];
// bf16 split buffers
__device__ __nv_bfloat16 g_ah[(size_t)NM*FFD];
__device__ __nv_bfloat16 g_al[(size_t)NM*FFD];
__device__ __nv_bfloat16 g_wh[(size_t)CD*FFD];   // weights transposed [N,K]
__device__ __nv_bfloat16 g_wl[(size_t)CD*FFD];

__device__ __forceinline__ float* buf(int which) {
    switch (which) {
        case 0: return g_x;
        case 1: return g_h;
        case 2: return g_q;
        case 3: return g_k;
        case 4: return g_v;
        case 5: return g_o;
        default: return g_ff;
    }
}

// ------------------------- PTX helpers -------------------------------------
__device__ __forceinline__ u32 smem_u32(const void* p) {
    u32 a;
    asm("{ .reg .u64 t; cvta.to.shared.u64 t, %1; cvt.u32.u64 %0, t; }"
        : "=r"(a) : "l"(p));
    return a;
}
#define SWZ(o) ((o) ^ (((o) >> 3) & 0x70))

#define CP_ASYNC16(dst, src) \
    asm volatile("cp.async.cg.shared.global [%0], [%1], 16;" \
                 :: "r"(dst), "l"(src) : "memory")
#define CP_COMMIT() asm volatile("cp.async.commit_group;" ::: "memory")
#define CP_WAIT0()  asm volatile("cp.async.wait_group 0;" ::: "memory")
#define CP_WAIT1()  asm volatile("cp.async.wait_group 1;" ::: "memory")

#if HAS_TCGEN05
__device__ __forceinline__ u32 elect1() {
    u32 pred;
    asm volatile("{\n\t.reg .pred p;\n\telect.sync _|p, 0xFFFFFFFF;\n\t"
                 "selp.b32 %0, 1, 0, p;\n\t}" : "=r"(pred));
    return pred;
}
__device__ __forceinline__ void mbar_init(u32 addr, u32 cnt) {
    asm volatile("mbarrier.init.shared.b64 [%0], %1;" :: "r"(addr), "r"(cnt) : "memory");
}
__device__ __forceinline__ void mbar_wait(u32 addr, u32 phase) {
    asm volatile("{\n\t.reg .pred P;\n\t"
        "W_%=:\n\t"
        "mbarrier.try_wait.parity.acquire.cta.shared::cta.b64 P, [%0], %1, 0x989680;\n\t"
        "@P bra.uni D_%=;\n\t"
        "bra.uni W_%=;\n\t"
        "D_%=:\n\t}"
        :: "r"(addr), "r"(phase) : "memory");
}
__device__ __forceinline__ void mma_f16_ss(u32 d, u64 ad, u64 bd, u32 idesc, u32 acc) {
    asm volatile("{\n\t.reg .pred p;\n\tsetp.ne.u32 p, %5, 0;\n\t"
        "tcgen05.mma.cta_group::1.kind::f16 [%0], %1, %2, %3, {%4,%4,%4,%4}, p;\n\t}"
        :: "r"(d), "l"(ad), "l"(bd), "r"(idesc), "r"(0u), "r"(acc) : "memory");
}
#define SMEM_DESC_BASE ((2ull<<61)|(1ull<<46)|(64ull<<32)|(1ull<<16))
#define MKDESC(a) (SMEM_DESC_BASE | ((u64)((a) >> 4) & 0x3FFFull))
#define IDESC_128 0x8200490u   // F32 acc, BF16xBF16, M=128, N=128

#define LDTM32(r, ta) \
    asm volatile("tcgen05.ld.sync.aligned.32x32b.x32.b32 " \
        "{%0,%1,%2,%3,%4,%5,%6,%7,%8,%9,%10,%11,%12,%13,%14,%15," \
        "%16,%17,%18,%19,%20,%21,%22,%23,%24,%25,%26,%27,%28,%29,%30,%31}, [%32];" \
        : "=r"((r)[0]),"=r"((r)[1]),"=r"((r)[2]),"=r"((r)[3]), \
          "=r"((r)[4]),"=r"((r)[5]),"=r"((r)[6]),"=r"((r)[7]), \
          "=r"((r)[8]),"=r"((r)[9]),"=r"((r)[10]),"=r"((r)[11]), \
          "=r"((r)[12]),"=r"((r)[13]),"=r"((r)[14]),"=r"((r)[15]), \
          "=r"((r)[16]),"=r"((r)[17]),"=r"((r)[18]),"=r"((r)[19]), \
          "=r"((r)[20]),"=r"((r)[21]),"=r"((r)[22]),"=r"((r)[23]), \
          "=r"((r)[24]),"=r"((r)[25]),"=r"((r)[26]),"=r"((r)[27]), \
          "=r"((r)[28]),"=r"((r)[29]),"=r"((r)[30]),"=r"((r)[31]) \
        : "r"(ta))
#else
#define LDSM4(r0, r1, r2, r3, addr) \
    asm volatile("ldmatrix.sync.aligned.m8n8.x4.shared.b16 {%0,%1,%2,%3}, [%4];" \
                 : "=r"(r0), "=r"(r1), "=r"(r2), "=r"(r3) : "r"(addr))
#define HMMA(d, a, b) \
    asm volatile("mma.sync.aligned.m16n8k16.row.col.f32.bf16.bf16.f32 " \
        "{%0,%1,%2,%3}, {%4,%5,%6,%7}, {%8,%9}, {%0,%1,%2,%3};" \
        : "+f"((d)[0]), "+f"((d)[1]), "+f"((d)[2]), "+f"((d)[3]) \
        : "r"((a)[0]), "r"((a)[1]), "r"((a)[2]), "r"((a)[3]), \
          "r"((b)[0]), "r"((b)[1]))
#endif

// ------------------------- embedding ---------------------------------------
__global__ void __launch_bounds__(256) embed_kernel(
        const int* __restrict__ idx, const float* __restrict__ tok,
        const float* __restrict__ pos) {
    int row = blockIdx.x;
    int t = row & (NT - 1);
    int token = idx[row];
    const float4* t4 = (const float4*)(tok + (size_t)token * CD);
    const float4* p4 = (const float4*)(pos + (size_t)t * CD);
    float4 a = t4[threadIdx.x];
    float4 b = p4[threadIdx.x];
    a.x += b.x; a.y += b.y; a.z += b.z; a.w += b.w;
    ((float4*)(g_x + (size_t)row * CD))[threadIdx.x] = a;
}

// ------------------------- layernorm ---------------------------------------
__global__ void __launch_bounds__(256) ln_kernel(
        int src, const float* __restrict__ g, const float* __restrict__ b, int dst) {
    __shared__ float rs[8], rss[8];
    __shared__ float mean_s, rstd_s;
    const float* x = buf(src);
    float* out = buf(dst);
    int row = blockIdx.x, tid = threadIdx.x;
    float4 v = ((const float4*)(x + (size_t)row * CD))[tid];
    float s  = v.x + v.y + v.z + v.w;
    float ss = v.x*v.x + v.y*v.y + v.z*v.z + v.w*v.w;
    #pragma unroll
    for (int o = 16; o; o >>= 1) {
        s  += __shfl_xor_sync(0xffffffffu, s,  o);
        ss += __shfl_xor_sync(0xffffffffu, ss, o);
    }
    if ((tid & 31) == 0) { rs[tid >> 5] = s; rss[tid >> 5] = ss; }
    __syncthreads();
    if (tid == 0) {
        float S = 0.f, SS = 0.f;
        #pragma unroll
        for (int i = 0; i < 8; i++) { S += rs[i]; SS += rss[i]; }
        float mean = S * (1.f / CD);
        float var  = SS * (1.f / CD) - mean * mean;
        mean_s = mean;
        rstd_s = rsqrtf(var + 1e-5f);
    }
    __syncthreads();
    float mean = mean_s, rstd = rstd_s;
    float4 gg = ((const float4*)g)[tid];
    float4 bb = ((const float4*)b)[tid];
    float4 o4;
    o4.x = (v.x - mean) * rstd * gg.x + bb.x;
    o4.y = (v.y - mean) * rstd * gg.y + bb.y;
    o4.z = (v.z - mean) * rstd * gg.z + bb.z;
    o4.w = (v.w - mean) * rstd * gg.w + bb.w;
    ((float4*)(out + (size_t)row * CD))[tid] = o4;
}

// ------------------------- bf16 hi/lo splits -------------------------------
__global__ void __launch_bounds__(256) split_act_kernel(int src) {
    size_t i = ((size_t)blockIdx.x * 256 + threadIdx.x) * 4;
    float4 a = *(const float4*)(buf(src) + i);
    __nv_bfloat16 h0 = __float2bfloat16(a.x);
    __nv_bfloat16 h1 = __float2bfloat16(a.y);
    __nv_bfloat16 h2 = __float2bfloat16(a.z);
    __nv_bfloat16 h3 = __float2bfloat16(a.w);
    __nv_bfloat16 l0 = __float2bfloat16(a.x - __bfloat162float(h0));
    __nv_bfloat16 l1 = __float2bfloat16(a.y - __bfloat162float(h1));
    __nv_bfloat16 l2 = __float2bfloat16(a.z - __bfloat162float(h2));
    __nv_bfloat16 l3 = __float2bfloat16(a.w - __bfloat162float(h3));
    __nv_bfloat162* oh = (__nv_bfloat162*)(g_ah + i);
    __nv_bfloat162* ol = (__nv_bfloat162*)(g_al + i);
    oh[0] = __nv_bfloat162(h0, h1); oh[1] = __nv_bfloat162(h2, h3);
    ol[0] = __nv_bfloat162(l0, l1); ol[1] = __nv_bfloat162(l2, l3);
}

// W[K,N] fp32 -> g_wh/g_wl [N,K] bf16 (transposed, K contiguous)
__global__ void __launch_bounds__(256) split_w_kernel(
        const float* __restrict__ W, int K, int N) {
    __shared__ float t[32][33];
    int n0 = blockIdx.x * 32, k0 = blockIdx.y * 32;
    int tx = threadIdx.x & 31, ty = threadIdx.x >> 5;
    #pragma unroll
    for (int i = 0; i < 4; i++)
        t[ty + i * 8][tx] = W[(size_t)(k0 + ty + i * 8) * N + n0 + tx];
    __syncthreads();
    #pragma unroll
    for (int i = 0; i < 4; i++) {
        int n = ty + i * 8;
        float a = t[tx][n];
        __nv_bfloat16 hi = __float2bfloat16(a);
        float lo = a - __bfloat162float(hi);
        size_t o = (size_t)(n0 + n) * K + k0 + tx;
        g_wh[o] = hi;
        g_wl[o] = __float2bfloat16(lo);
    }
}

// ------------------------- bf16-split GEMM ---------------------------------
// C[M,N] = act( (Ah+Al)[M,K] @ (Bh+Bl)^T[N,K] + bias ) (+res)
// Tile 128x128, BK=64, 2-stage cp.async. 3 terms: AhBh + AhBl + AlBh.
#define BM 128
#define BN 128
#define BK 64
#define OFF_AH 0
#define OFF_AL 16384
#define OFF_BH 32768
#define OFF_BL 49152
#define STAGE  65536
#define GEMM_SMEM (2*STAGE + 2048)

__device__ __forceinline__ void load_stage_async(
        u32 stg, const __nv_bfloat16* __restrict__ Bh,
        const __nv_bfloat16* __restrict__ Bl,
        int m0, int n0, int k0, int K, int tid) {
    int r = tid >> 1, h = tid & 1;
    size_t aoff = (size_t)(m0 + r) * K + k0;
    size_t boff = (size_t)(n0 + r) * K + k0;
    #pragma unroll
    for (int j = 0; j < 4; j++) {
        int c = h * 4 + j;
        u32 so = SWZ((u32)(r * 128 + c * 16));
        CP_ASYNC16(stg + OFF_AH + so, (const void*)(g_ah + aoff + c * 8));
        CP_ASYNC16(stg + OFF_AL + so, (const void*)(g_al + aoff + c * 8));
        CP_ASYNC16(stg + OFF_BH + so, (const void*)(Bh + boff + c * 8));
        CP_ASYNC16(stg + OFF_BL + so, (const void*)(Bl + boff + c * 8));
    }
}

template<bool RELU, bool RES>
__global__ void __launch_bounds__(256, 1) tcgemm_kernel(
        const float* __restrict__ bias, int rsel, int osel, int N, int K) {
    extern __shared__ char dsm[];
    u32 sb = (smem_u32(dsm) + 1023u) & ~1023u;
    int tid = threadIdx.x, wid = tid >> 5, lid = tid & 31;
    int m0 = blockIdx.y * BM, n0 = blockIdx.x * BN;
    const int NS = K >> 6;
    const float* res = buf(rsel);
    float* out = buf(osel);

#if HAS_TCGEN05
    // ================= tcgen05 path =================
    const u32 TM_PTR = sb + 2 * STAGE;
    const u32 MB0 = TM_PTR + 8, MB1 = TM_PTR + 16;

    if (wid == 0) {
        asm volatile("tcgen05.alloc.cta_group::1.sync.aligned.shared::cta.b32 [%0], %1;"
                     :: "r"(TM_PTR), "r"(128u) : "memory");
        asm volatile("tcgen05.relinquish_alloc_permit.cta_group::1.sync.aligned;");
    }
    if (tid == 0) { mbar_init(MB0, 1); mbar_init(MB1, 1); }
    __syncthreads();
    u32 tmem;
    asm("ld.shared.b32 %0, [%1];" : "=r"(tmem) : "r"(TM_PTR));

    load_stage_async(sb, g_wh, g_wl, m0, n0, 0, K, tid);
    CP_COMMIT();
    CP_WAIT0();
    __syncthreads();

    u32 ph0 = 0, ph1 = 0;
    for (int s = 0; ; s++) {
        int b = s & 1;
        u32 stg = sb + b * STAGE;
        if (wid == 0) {
            asm volatile("fence.proxy.async.shared::cta;" ::: "memory");
            if (elect1()) {
                u64 dah = MKDESC(stg + OFF_AH);
                u64 dal = MKDESC(stg + OFF_AL);
                u64 dbh = MKDESC(stg + OFF_BH);
                u64 dbl = MKDESC(stg + OFF_BL);
                #pragma unroll
                for (int kk = 0; kk < 4; kk++) {
                    mma_f16_ss(tmem, dah + kk * 2, dbh + kk * 2, IDESC_128,
                               (s == 0 && kk == 0) ? 0u : 1u);
                    mma_f16_ss(tmem, dah + kk * 2, dbl + kk * 2, IDESC_128, 1u);
                    mma_f16_ss(tmem, dal + kk * 2, dbh + kk * 2, IDESC_128, 1u);
                }
                asm volatile(
                    "tcgen05.commit.cta_group::1.mbarrier::arrive::one.shared::cluster.b64 [%0];"
                    :: "r"(b ? MB1 : MB0) : "memory");
            }
        }
        if (s + 1 == NS) break;
        if (s >= 1) {
            if (b) { mbar_wait(MB0, ph0); ph0 ^= 1u; }
            else   { mbar_wait(MB1, ph1); ph1 ^= 1u; }
        }
        load_stage_async(sb + (b ^ 1) * STAGE, g_wh, g_wl, m0, n0, (s + 1) << 6, K, tid);
        CP_COMMIT();
        CP_WAIT0();
        __syncthreads();
    }
    if ((NS - 1) & 1) mbar_wait(MB1, ph1);
    else              mbar_wait(MB0, ph0);
    asm volatile("tcgen05.fence::after_thread_sync;" ::: "memory");

    if (wid < 4) {
        size_t m = (size_t)m0 + wid * 32 + lid;
        for (int c0 = 0; c0 < BN; c0 += 32) {
            u32 r[32];
            LDTM32(r, tmem + c0);
            asm volatile("tcgen05.wait::ld.sync.aligned;" ::: "memory");
            #pragma unroll
            for (int q = 0; q < 8; q++) {
                int n = n0 + c0 + q * 4;
                float c0f = __uint_as_float(r[q * 4 + 0]);
                float c1f = __uint_as_float(r[q * 4 + 1]);
                float c2f = __uint_as_float(r[q * 4 + 2]);
                float c3f = __uint_as_float(r[q * 4 + 3]);
                if (bias) {
                    float4 bv = *(const float4*)&bias[n];
                    c0f += bv.x; c1f += bv.y; c2f += bv.z; c3f += bv.w;
                }
                if (RELU) {
                    c0f = fmaxf(c0f, 0.f); c1f = fmaxf(c1f, 0.f);
                    c2f = fmaxf(c2f, 0.f); c3f = fmaxf(c3f, 0.f);
                }
                if (RES) {
                    float4 rv = *(const float4*)&res[m * N + n];
                    c0f += rv.x; c1f += rv.y; c2f += rv.z; c3f += rv.w;
                }
                *(float4*)&out[m * N + n] = make_float4(c0f, c1f, c2f, c3f);
            }
        }
    }
    __syncthreads();
    if (wid == 0) {
        asm volatile("tcgen05.dealloc.cta_group::1.sync.aligned.b32 %0, %1;"
                     :: "r"(tmem), "r"(128u));
    }
#else
    // ================= mma.sync (HMMA) fallback =================
    int wm = wid & 1;          // 0..1 -> 64-row half
    int wn = wid >> 1;         // 0..3 -> 32-col slab
    int lane = lid;
    float acc[4][4][4];
    #pragma unroll
    for (int i = 0; i < 4; i++)
        #pragma unroll
        for (int j = 0; j < 4; j++)
            #pragma unroll
            for (int c = 0; c < 4; c++) acc[i][j][c] = 0.f;

    // ldmatrix lane addressing (within tile, bytes before swizzle)
    int a_row = wm * 64 + (lane & 15);          // + mf*16
    int a_kb  = (lane >> 4) * 16;               // + kk*32
    int b_row = wn * 32 + ((lane >> 4) << 3) + (lane & 7);   // + nf2*16
    int b_kb  = ((lane >> 3) & 1) * 16;         // + kk*32

    load_stage_async(sb, g_wh, g_wl, m0, n0, 0, K, tid);
    CP_COMMIT();
    for (int s = 0; s < NS; s++) {
        int b = s & 1;
        u32 stg = sb + b * STAGE;
        if (s + 1 < NS) {
            load_stage_async(sb + (b ^ 1) * STAGE, g_wh, g_wl, m0, n0,
                             (s + 1) << 6, K, tid);
            CP_COMMIT();
            CP_WAIT1();
        } else {
            CP_WAIT0();
        }
        __syncthreads();

        #pragma unroll
        for (int kk = 0; kk < 4; kk++) {
            u32 ah[4][4], al[4][4];
            #pragma unroll
            for (int mf = 0; mf < 4; mf++) {
                u32 off = SWZ((u32)((a_row + mf * 16) * 128 + kk * 32 + a_kb));
                LDSM4(ah[mf][0], ah[mf][1], ah[mf][2], ah[mf][3], stg + OFF_AH + off);
                LDSM4(al[mf][0], al[mf][1], al[mf][2], al[mf][3], stg + OFF_AL + off);
            }
            u32 bh[4][2], bl[4][2];
            #pragma unroll
            for (int nf2 = 0; nf2 < 2; nf2++) {
                u32 off = SWZ((u32)((b_row + nf2 * 16) * 128 + kk * 32 + b_kb));
                u32 t0, t1, t2, t3;
                LDSM4(t0, t1, t2, t3, stg + OFF_BH + off);
                bh[nf2*2+0][0] = t0; bh[nf2*2+0][1] = t1;
                bh[nf2*2+1][0] = t2; bh[nf2*2+1][1] = t3;
                LDSM4(t0, t1, t2, t3, stg + OFF_BL + off);
                bl[nf2*2+0][0] = t0; bl[nf2*2+0][1] = t1;
                bl[nf2*2+1][0] = t2; bl[nf2*2+1][1] = t3;
            }
            #pragma unroll
            for (int mf = 0; mf < 4; mf++)
                #pragma unroll
                for (int nf = 0; nf < 4; nf++) {
                    HMMA(acc[mf][nf], ah[mf], bh[nf]);
                    HMMA(acc[mf][nf], ah[mf], bl[nf]);
                    HMMA(acc[mf][nf], al[mf], bh[nf]);
                }
        }
        __syncthreads();
    }

    // epilogue
    int gid = lane >> 2, qid = lane & 3;
    #pragma unroll
    for (int mf = 0; mf < 4; mf++) {
        #pragma unroll
        for (int nf = 0; nf < 4; nf++) {
            int n = n0 + wn * 32 + nf * 8 + qid * 2;
            size_t r0 = (size_t)(m0 + wm * 64 + mf * 16 + gid);
            size_t r1 = r0 + 8;
            float c0 = acc[mf][nf][0], c1 = acc[mf][nf][1];
            float c2 = acc[mf][nf][2], c3 = acc[mf][nf][3];
            if (bias) {
                float2 bv = *(const float2*)&bias[n];
                c0 += bv.x; c1 += bv.y; c2 += bv.x; c3 += bv.y;
            }
            if (RELU) {
                c0 = fmaxf(c0, 0.f); c1 = fmaxf(c1, 0.f);
                c2 = fmaxf(c2, 0.f); c3 = fmaxf(c3, 0.f);
            }
            if (RES) {
                float2 r0v = *(const float2*)&res[r0 * N + n];
                float2 r1v = *(const float2*)&res[r1 * N + n];
                c0 += r0v.x; c1 += r0v.y; c2 += r1v.x; c3 += r1v.y;
            }
            *(float2*)&out[r0 * N + n] = make_float2(c0, c1);
            *(float2*)&out[r1 * N + n] = make_float2(c2, c3);
        }
    }
#endif
}

// ------------------------- flash attention (fp32) --------------------------
__global__ void __launch_bounds__(256) attn_kernel() {
    __shared__ float Qt[64][64];
    __shared__ float KP[64][64];
    __shared__ float Vs[64][64];
    const float* q = g_q;
    const float* k = g_k;
    const float* v = g_v;
    float* o = g_o;

    int bh = blockIdx.x;
    int b = bh >> 4, h = bh & 15;
    int qb = blockIdx.y;
    int tid = threadIdx.x;
    int tx = tid & 15, ty = tid >> 4;
    const size_t base = (size_t)b * NT * CD + h * HSD;

    {
        int r0 = tid >> 4;
        int d0 = (tid & 15) * 4;
        #pragma unroll
        for (int rr = 0; rr < 64; rr += 16) {
            int r = r0 + rr;
            float4 t = *(const float4*)&q[base + (size_t)(qb * 64 + r) * CD + d0];
            Qt[d0 + 0][r] = t.x; Qt[d0 + 1][r] = t.y;
            Qt[d0 + 2][r] = t.z; Qt[d0 + 3][r] = t.w;
        }
    }

    float m_i[4], l_i[4], acc[4][4];
    #pragma unroll
    for (int i = 0; i < 4; i++) {
        m_i[i] = -1e30f; l_i[i] = 0.f;
        #pragma unroll
        for (int j = 0; j < 4; j++) acc[i][j] = 0.f;
    }
    const float scale = 0.125f;

    for (int kb = 0; kb <= qb; kb++) {
        __syncthreads();
        {
            int r0 = tid >> 4;
            int d0 = (tid & 15) * 4;
            #pragma unroll
            for (int rr = 0; rr < 64; rr += 16) {
                int r = r0 + rr;
                float4 t = *(const float4*)&k[base + (size_t)(kb * 64 + r) * CD + d0];
                KP[d0 + 0][r] = t.x; KP[d0 + 1][r] = t.y;
                KP[d0 + 2][r] = t.z; KP[d0 + 3][r] = t.w;
                float4 u = *(const float4*)&v[base + (size_t)(kb * 64 + r) * CD + d0];
                *(float4*)&Vs[r][d0] = u;
            }
        }
        __syncthreads();

        float s[4][4];
        #pragma unroll
        for (int i = 0; i < 4; i++)
            #pragma unroll
            for (int j = 0; j < 4; j++) s[i][j] = 0.f;
        for (int d = 0; d < 64; d++) {
            float4 a = *(const float4*)&Qt[d][ty * 4];
            float4 bb = *(const float4*)&KP[d][tx * 4];
            float av[4] = {a.x, a.y, a.z, a.w};
            float bv[4] = {bb.x, bb.y, bb.z, bb.w};
            #pragma unroll
            for (int i = 0; i < 4; i++)
                #pragma unroll
                for (int j = 0; j < 4; j++) s[i][j] += av[i] * bv[j];
        }
        if (kb == qb) {
            #pragma unroll
            for (int i = 0; i < 4; i++)
                #pragma unroll
                for (int j = 0; j < 4; j++)
                    s[i][j] = (tx * 4 + j > ty * 4 + i) ? -1e30f : s[i][j] * scale;
        } else {
            #pragma unroll
            for (int i = 0; i < 4; i++)
                #pragma unroll
                for (int j = 0; j < 4; j++) s[i][j] *= scale;
        }

        float p[4][4];
        #pragma unroll
        for (int i = 0; i < 4; i++) {
            float tm = fmaxf(fmaxf(s[i][0], s[i][1]), fmaxf(s[i][2], s[i][3]));
            #pragma unroll
            for (int off = 8; off; off >>= 1)
                tm = fmaxf(tm, __shfl_xor_sync(0xffffffffu, tm, off));
            float nm = fmaxf(m_i[i], tm);
            float corr = __expf(m_i[i] - nm);
            float rs = 0.f;
            #pragma unroll
            for (int j = 0; j < 4; j++) {
                p[i][j] = __expf(s[i][j] - nm);
                rs += p[i][j];
            }
            #pragma unroll
            for (int off = 8; off; off >>= 1)
                rs += __shfl_xor_sync(0xffffffffu, rs, off);
            l_i[i] = l_i[i] * corr + rs;
            m_i[i] = nm;
            #pragma unroll
            for (int j = 0; j < 4; j++) acc[i][j] *= corr;
        }

        __syncthreads();
        #pragma unroll
        for (int i = 0; i < 4; i++)
            *(float4*)&KP[ty * 4 + i][tx * 4] =
                make_float4(p[i][0], p[i][1], p[i][2], p[i][3]);
        __syncthreads();

        for (int kk = 0; kk < 64; kk += 4) {
            float pr[4][4];
            #pragma unroll
            for (int i = 0; i < 4; i++) {
                float4 t = *(const float4*)&KP[ty * 4 + i][kk];
                pr[i][0] = t.x; pr[i][1] = t.y; pr[i][2] = t.z; pr[i][3] = t.w;
            }
            #pragma unroll
            for (int kq = 0; kq < 4; kq++) {
                float4 vv = *(const float4*)&Vs[kk + kq][tx * 4];
                #pragma unroll
                for (int i = 0; i < 4; i++) {
                    acc[i][0] += pr[i][kq] * vv.x;
                    acc[i][1] += pr[i][kq] * vv.y;
                    acc[i][2] += pr[i][kq] * vv.z;
                    acc[i][3] += pr[i][kq] * vv.w;
                }
            }
        }
    }

    #pragma unroll
    for (int i = 0; i < 4; i++) {
        float inv = 1.f / l_i[i];
        float4 r = make_float4(acc[i][0] * inv, acc[i][1] * inv,
                               acc[i][2] * inv, acc[i][3] * inv);
        *(float4*)&o[base + (size_t)(qb * 64 + ty * 4 + i) * CD + tx * 4] = r;
    }
}

// ------------------------- LM head (N=67) ----------------------------------
__global__ void __launch_bounds__(128) lm_kernel(
        const float* __restrict__ W, const float* __restrict__ bias,
        float* __restrict__ out) {
    __shared__ float hs[CD];
    const float* h = g_h;
    int row = blockIdx.x;
    int tid = threadIdx.x;
    ((float4*)hs)[tid]       = ((const float4*)(h + (size_t)row * CD))[tid];
    ((float4*)hs)[tid + 128] = ((const float4*)(h + (size_t)row * CD))[tid + 128];
    __syncthreads();
    if (tid < NV) {
        float a0 = 0.f, a1 = 0.f, a2 = 0.f, a3 = 0.f;
        #pragma unroll 4
        for (int kk = 0; kk < CD; kk += 4) {
            a0 += hs[kk + 0] * W[(kk + 0) * NV + tid];
            a1 += hs[kk + 1] * W[(kk + 1) * NV + tid];
            a2 += hs[kk + 2] * W[(kk + 2) * NV + tid];
            a3 += hs[kk + 3] * W[(kk + 3) * NV + tid];
        }
        out[(size_t)row * NV + tid] = bias[tid] + ((a0 + a1) + (a2 + a3));
    }
}

// ------------------------- launch ------------------------------------------
extern "C" void kernel_launch(void* const* d_in, const int* in_sizes, int n_in,
                              void* d_out, int out_size) {
    const int*   idx  = (const int*)  d_in[0];
    const float* tok  = (const float*)d_in[1];
    const float* pos  = (const float*)d_in[2];
    const float* Wq   = (const float*)d_in[3];
    const float* Wk   = (const float*)d_in[4];
    const float* Wv   = (const float*)d_in[5];
    const float* Wo   = (const float*)d_in[6];
    const float* bo   = (const float*)d_in[7];
    const float* ln1g = (const float*)d_in[8];
    const float* ln1b = (const float*)d_in[9];
    const float* ln2g = (const float*)d_in[10];
    const float* ln2b = (const float*)d_in[11];
    const float* W1   = (const float*)d_in[12];
    const float* b1   = (const float*)d_in[13];
    const float* W2   = (const float*)d_in[14];
    const float* b2   = (const float*)d_in[15];
    const float* lnfg = (const float*)d_in[16];
    const float* lnfb = (const float*)d_in[17];
    const float* Wlm  = (const float*)d_in[18];
    const float* blm  = (const float*)d_in[19];
    float* out = (float*)d_out;

    cudaFuncSetAttribute(tcgemm_kernel<false, false>,
                         cudaFuncAttributeMaxDynamicSharedMemorySize, GEMM_SMEM);
    cudaFuncSetAttribute(tcgemm_kernel<false, true>,
                         cudaFuncAttributeMaxDynamicSharedMemorySize, GEMM_SMEM);
    cudaFuncSetAttribute(tcgemm_kernel<true, false>,
                         cudaFuncAttributeMaxDynamicSharedMemorySize, GEMM_SMEM);

    dim3 gC(CD / BN, NM / BM);      // (8, 64)
    dim3 gF(FFD / BN, NM / BM);     // (32, 64)
    dim3 wC(CD / 32, CD / 32);
    dim3 w1(FFD / 32, CD / 32);
    dim3 w2(CD / 32, FFD / 32);
    int  saC  = NM * CD / 1024;
    int  saF  = NM * FFD / 1024;

    embed_kernel<<<NM, 256>>>(idx, tok, pos);
    for (int l = 0; l < NL; l++) {
        ln_kernel<<<NM, 256>>>(0, ln1g + (size_t)l * CD, ln1b + (size_t)l * CD, 1);
        split_act_kernel<<<saC, 256>>>(1);
        split_w_kernel<<<wC, 256>>>(Wq + (size_t)l * CD * CD, CD, CD);
        tcgemm_kernel<false, false><<<gC, 256, GEMM_SMEM>>>(nullptr, 0, 2, CD, CD);
        split_w_kernel<<<wC, 256>>>(Wk + (size_t)l * CD * CD, CD, CD);
        tcgemm_kernel<false, false><<<gC, 256, GEMM_SMEM>>>(nullptr, 0, 3, CD, CD);
        split_w_kernel<<<wC, 256>>>(Wv + (size_t)l * CD * CD, CD, CD);
        tcgemm_kernel<false, false><<<gC, 256, GEMM_SMEM>>>(nullptr, 0, 4, CD, CD);
        attn_kernel<<<dim3(NB * NH, NT / 64), 256>>>();
        split_act_kernel<<<saC, 256>>>(5);
        split_w_kernel<<<wC, 256>>>(Wo + (size_t)l * CD * CD, CD, CD);
        tcgemm_kernel<false, true><<<gC, 256, GEMM_SMEM>>>(bo + (size_t)l * CD, 0, 0, CD, CD);
        ln_kernel<<<NM, 256>>>(0, ln2g + (size_t)l * CD, ln2b + (size_t)l * CD, 1);
        split_act_kernel<<<saC, 256>>>(1);
        split_w_kernel<<<w1, 256>>>(W1 + (size_t)l * CD * FFD, CD, FFD);
        tcgemm_kernel<true, false><<<gF, 256, GEMM_SMEM>>>(b1 + (size_t)l * FFD, 0, 6, FFD, CD);
        split_act_kernel<<<saF, 256>>>(6);
        split_w_kernel<<<w2, 256>>>(W2 + (size_t)l * FFD * CD, FFD, CD);
        tcgemm_kernel<false, true><<<gC, 256, GEMM_SMEM>>>(b2 + (size_t)l * CD, 0, 0, CD, FFD);
    }
    ln_kernel<<<NM, 256>>>(0, lnfg, lnfb, 1);
    lm_kernel<<<NM, 128>>>(Wlm, blm, out);
}